// round 7
// baseline (speedup 1.0000x reference)
#include <cuda_runtime.h>
#include <math.h>

#define IN_C   32
#define OUT_C  64
#define HH     56
#define WWID   56
#define TILE_H 4
#define TILE_W 8
#define PADH   (TILE_H + 2)          // 6
#define PADW   (TILE_W + 2)          // 10
#define NELEM  (PADH * PADW)         // 60
#define BSTRIDE 12                   // bases smem row stride (floats): float4-aligned

// One-time reorganized weights (device scratch; no allocation).
// g_ws[((c*9 + kk)*8 + f)*64 + o] = ws[o*2304 + (c*9+kk)*8 + f]
// g_wb[((c*9 + kk))*64 + o]       = wb[o*288 + c*9 + kk]
__device__ float g_ws[IN_C * 9 * 8 * OUT_C];   // 147456 floats
__device__ float g_wb[IN_C * 9 * OUT_C];       // 18432 floats

__global__ __launch_bounds__(256)
void kan_reorg_kernel(const float* __restrict__ ws, const float* __restrict__ wb)
{
    const int idx = blockIdx.x * blockDim.x + threadIdx.x;
    if (idx < IN_C * 9 * 8 * OUT_C) {
        const int o = idx & 63;
        const int f = (idx >> 6) & 7;
        const int r = idx >> 9;            // c*9 + kk
        g_ws[idx] = ws[o * 2304 + r * 8 + f];
    }
    if (idx < IN_C * 9 * OUT_C) {
        const int o = idx & 63;
        const int r = idx >> 6;            // c*9 + kk
        g_wb[idx] = wb[o * 288 + r];
    }
}

__global__ __launch_bounds__(128)
void kan_fused_kernel(const float* __restrict__ x,
                      const float* __restrict__ scaler,
                      float* __restrict__ out)
{
    __shared__ __align__(16) float s_x[NELEM];
    __shared__ __align__(16) float s_b[NELEM * BSTRIDE];
    __shared__ __align__(16) float s_ws[9 * 8 * OUT_C];   // [kk][f][o]
    __shared__ __align__(16) float s_wb[9 * OUT_C];       // [kk][o]

    const int tid = threadIdx.x;
    const int og  = tid >> 3;     // 0..15 -> out channels og*4..og*4+3
    const int pg  = tid & 7;      // 0..7  -> output column within tile
    const int tw0 = blockIdx.x * TILE_W;
    const int th0 = blockIdx.y * TILE_H;
    const int b   = blockIdx.z;

    float accS[4][4];   // [oi][p]
    float accB[4][4];
    #pragma unroll
    for (int i = 0; i < 4; i++)
        #pragma unroll
        for (int p = 0; p < 4; p++) { accS[i][p] = 0.f; accB[i][p] = 0.f; }

    for (int c = 0; c < IN_C; ++c) {
        __syncthreads();   // protect smem from previous iteration's readers

        // ---- stage x tile and compute B-spline bases (zero padding: bases(0) != 0) ----
        if (tid < NELEM) {
            const int rr = tid / PADW;
            const int cc = tid - rr * PADW;
            const int gh = th0 - 1 + rr;
            const int gw = tw0 - 1 + cc;
            float v = 0.f;
            if (gh >= 0 && gh < HH && gw >= 0 && gw < WWID)
                v = x[(((b * IN_C) + c) * HH + gh) * WWID + gw];
            s_x[tid] = v;

            float* bp = &s_b[tid * BSTRIDE];
            #pragma unroll
            for (int f = 0; f < 8; f++) bp[f] = 0.f;

            // uniform cubic B-spline, knots t_i = -2.2 + 0.4*i ; s = 2.5v + 5.5
            const float s  = fmaf(v, 2.5f, 5.5f);
            const float fj = floorf(s);
            const int   j  = (int)fj;
            if (j >= 0 && j <= 10) {
                const float u   = s - fj;
                const float u2  = u * u;
                const float u3  = u2 * u;
                const float omu = 1.f - u;
                const float w0 = omu * omu * omu * (1.f / 6.f);
                const float w1 = (3.f * u3 - 6.f * u2 + 4.f) * (1.f / 6.f);
                const float w2 = (-3.f * u3 + 3.f * u2 + 3.f * u + 1.f) * (1.f / 6.f);
                const float w3 = u3 * (1.f / 6.f);
                const int i0 = j - 3;               // nonzero bases i0..i0+3, clip to [0,7]
                if (i0 >= 0)             bp[i0]     = w0;
                if (i0 >= -1 && i0 <= 6) bp[i0 + 1] = w1;
                if (i0 >= -2 && i0 <= 5) bp[i0 + 2] = w2;
                if (i0 <= 4)             bp[i0 + 3] = w3;
            }
        }

        // ---- stage weights for this input channel: pure contiguous vec4 copy ----
        {
            const float4* src = (const float4*)&g_ws[c * (9 * 8 * OUT_C)];
            float4*       dst = (float4*)s_ws;
            #pragma unroll
            for (int l = 0; l < 9; l++)                 // 9*128 = 1152 float4 = 4608 floats
                dst[l * 128 + tid] = src[l * 128 + tid];

            // 9*64 = 576 floats = 144 float4 -> 128 threads + 16-thread tail
            const float4* srcb = (const float4*)&g_wb[c * (9 * OUT_C)];
            float4*       dstb = (float4*)s_wb;
            dstb[tid] = srcb[tid];
            if (tid < 16) dstb[128 + tid] = srcb[128 + tid];
        }
        __syncthreads();

        // ---- accumulate over the 3x3 taps ----
        #pragma unroll 1
        for (int kh = 0; kh < 3; ++kh) {
            #pragma unroll 1
            for (int kw = 0; kw < 3; ++kw) {
                const int kk = kh * 3 + kw;

                float4 b0[4], b1[4];
                float  xv[4];
                #pragma unroll
                for (int p = 0; p < 4; p++) {
                    const int idx = (p + kh) * PADW + pg + kw;
                    xv[p] = s_x[idx];
                    b0[p] = *(const float4*)&s_b[idx * BSTRIDE];
                    b1[p] = *(const float4*)&s_b[idx * BSTRIDE + 4];
                }

                // weights: [f][o] slice, float4 over o at this og -> conflict-free
                const float* wsk = &s_ws[kk * 8 * OUT_C];
                float4 wv4[8];
                #pragma unroll
                for (int f = 0; f < 8; f++)
                    wv4[f] = *(const float4*)&wsk[f * OUT_C + (og << 2)];
                const float* wvf = reinterpret_cast<const float*>(wv4);  // [f*4 + oi]
                const float4 wb4 = *(const float4*)&s_wb[kk * OUT_C + (og << 2)];
                const float* wbf = reinterpret_cast<const float*>(&wb4); // [oi]

                #pragma unroll
                for (int p = 0; p < 4; p++) {
                    const float bf[8] = { b0[p].x, b0[p].y, b0[p].z, b0[p].w,
                                          b1[p].x, b1[p].y, b1[p].z, b1[p].w };
                    #pragma unroll
                    for (int oi = 0; oi < 4; oi++) {
                        float t = accS[oi][p];
                        #pragma unroll
                        for (int f = 0; f < 8; f++)
                            t = fmaf(bf[f], wvf[f * 4 + oi], t);
                        accS[oi][p] = t;
                        accB[oi][p] = fmaf(xv[p], wbf[oi], accB[oi][p]);
                    }
                }
            }
        }
    }

    // ---- epilogue: silu(base) + scaler * spline ----
    #pragma unroll
    for (int oi = 0; oi < 4; oi++) {
        const int o  = (og << 2) + oi;
        const float sc = scaler[o];
        #pragma unroll
        for (int p = 0; p < 4; p++) {
            const int h = th0 + p;
            const int w = tw0 + pg;
            const float zb  = accB[oi][p];
            const float sil = zb / (1.f + expf(-zb));
            out[(((b * OUT_C) + o) * HH + h) * WWID + w] = fmaf(sc, accS[oi][p], sil);
        }
    }
}

extern "C" void kernel_launch(void* const* d_in, const int* in_sizes, int n_in,
                              void* d_out, int out_size)
{
    const float* x      = (const float*)d_in[0];
    const float* wb     = (const float*)d_in[1];
    const float* ws     = (const float*)d_in[2];
    const float* scaler = (const float*)d_in[3];
    float* out = (float*)d_out;

    // one-time weight reorg (cheap: 147K elements)
    kan_reorg_kernel<<<(IN_C * 9 * 8 * OUT_C + 255) / 256, 256>>>(ws, wb);

    const int B = in_sizes[0] / (IN_C * HH * WWID);   // 4
    dim3 grid(WWID / TILE_W, HH / TILE_H, B);         // (7, 14, 4) = 392 blocks
    kan_fused_kernel<<<grid, 128>>>(x, scaler, out);
}

// round 12
// speedup vs baseline: 1.2104x; 1.2104x over previous
#include <cuda_runtime.h>
#include <math.h>

#define IN_C   32
#define OUT_C  64
#define HH     56
#define WWID   56
#define BB     4
#define TILE_H 8
#define TILE_W 8
#define PADH   (TILE_H + 2)          // 10
#define PADW   (TILE_W + 2)          // 10
#define NELEM  (PADH * PADW)         // 100
#define BSTRIDE 12                   // bases smem row stride (floats)
#define NSPLIT 2
#define CCHUNK (IN_C / NSPLIT)       // 16
#define NOUT   (BB * OUT_C * HH * WWID)   // 802816

// One-time reorganized weights (device scratch; no allocation).
// g_ws[((c*9 + kk)*8 + f)*64 + o] = ws[o*2304 + (c*9+kk)*8 + f]
// g_wb[((c*9 + kk))*64 + o]       = wb[o*288 + c*9 + kk]
__device__ float g_ws[IN_C * 9 * 8 * OUT_C];
__device__ float g_wb[IN_C * 9 * OUT_C];
// Partial sums: [split][b][o][h][w]
__device__ float g_partS[NSPLIT * NOUT];
__device__ float g_partB[NSPLIT * NOUT];

__global__ __launch_bounds__(256)
void kan_reorg_kernel(const float* __restrict__ ws, const float* __restrict__ wb)
{
    const int idx = blockIdx.x * blockDim.x + threadIdx.x;
    if (idx < IN_C * 9 * 8 * OUT_C) {
        const int o = idx & 63;
        const int f = (idx >> 6) & 7;
        const int r = idx >> 9;            // c*9 + kk
        g_ws[idx] = ws[o * 2304 + r * 8 + f];
    }
    if (idx < IN_C * 9 * OUT_C) {
        const int o = idx & 63;
        const int r = idx >> 6;            // c*9 + kk
        g_wb[idx] = wb[o * 288 + r];
    }
}

__global__ __launch_bounds__(128)
void kan_partial_kernel(const float* __restrict__ x)
{
    __shared__ __align__(16) float s_x[NELEM];
    __shared__ __align__(16) float s_b[NELEM * BSTRIDE];
    __shared__ __align__(16) float s_ws[9 * 8 * OUT_C];   // [kk][f][o]
    __shared__ __align__(16) float s_wb[9 * OUT_C];       // [kk][o]

    const int tid   = threadIdx.x;
    const int og    = tid >> 3;     // 0..15 -> out channels og*4..og*4+3
    const int pg    = tid & 7;      // 0..7  -> output column within tile
    const int tw0   = blockIdx.x * TILE_W;
    const int th0   = blockIdx.y * TILE_H;
    const int b     = blockIdx.z >> 1;
    const int split = blockIdx.z & 1;
    const int c0    = split * CCHUNK;

    float accS[4][TILE_H];   // [oi][p]
    float accB[4][TILE_H];
    #pragma unroll
    for (int i = 0; i < 4; i++)
        #pragma unroll
        for (int p = 0; p < TILE_H; p++) { accS[i][p] = 0.f; accB[i][p] = 0.f; }

    for (int ci = 0; ci < CCHUNK; ++ci) {
        const int c = c0 + ci;
        __syncthreads();   // protect smem from previous iteration's readers

        // ---- stage x tile and compute B-spline bases (zero padding: bases(0) != 0) ----
        if (tid < NELEM) {
            const int rr = tid / PADW;
            const int cc = tid - rr * PADW;
            const int gh = th0 - 1 + rr;
            const int gw = tw0 - 1 + cc;
            float v = 0.f;
            if (gh >= 0 && gh < HH && gw >= 0 && gw < WWID)
                v = x[(((b * IN_C) + c) * HH + gh) * WWID + gw];
            s_x[tid] = v;

            float* bp = &s_b[tid * BSTRIDE];
            #pragma unroll
            for (int f = 0; f < 8; f++) bp[f] = 0.f;

            // uniform cubic B-spline, knots t_i = -2.2 + 0.4*i ; s = 2.5v + 5.5
            const float s  = fmaf(v, 2.5f, 5.5f);
            const float fj = floorf(s);
            const int   j  = (int)fj;
            if (j >= 0 && j <= 10) {
                const float u   = s - fj;
                const float u2  = u * u;
                const float u3  = u2 * u;
                const float omu = 1.f - u;
                const float w0 = omu * omu * omu * (1.f / 6.f);
                const float w1 = (3.f * u3 - 6.f * u2 + 4.f) * (1.f / 6.f);
                const float w2 = (-3.f * u3 + 3.f * u2 + 3.f * u + 1.f) * (1.f / 6.f);
                const float w3 = u3 * (1.f / 6.f);
                const int i0 = j - 3;               // nonzero bases i0..i0+3, clip to [0,7]
                if (i0 >= 0)             bp[i0]     = w0;
                if (i0 >= -1 && i0 <= 6) bp[i0 + 1] = w1;
                if (i0 >= -2 && i0 <= 5) bp[i0 + 2] = w2;
                if (i0 <= 4)             bp[i0 + 3] = w3;
            }
        }

        // ---- stage weights for this input channel: contiguous vec4 copy ----
        {
            const float4* src = (const float4*)&g_ws[c * (9 * 8 * OUT_C)];
            float4*       dst = (float4*)s_ws;
            #pragma unroll
            for (int l = 0; l < 9; l++)
                dst[l * 128 + tid] = src[l * 128 + tid];

            const float4* srcb = (const float4*)&g_wb[c * (9 * OUT_C)];
            float4*       dstb = (float4*)s_wb;
            dstb[tid] = srcb[tid];
            if (tid < 16) dstb[128 + tid] = srcb[128 + tid];
        }
        __syncthreads();

        // ---- accumulate over the 3x3 taps ----
        #pragma unroll 1
        for (int kh = 0; kh < 3; ++kh) {
            #pragma unroll 1
            for (int kw = 0; kw < 3; ++kw) {
                const int kk = kh * 3 + kw;

                // weights: [f][o] slice, float4 over o at this og (broadcast over pg)
                const float* wsk = &s_ws[kk * 8 * OUT_C];
                float4 wv4[8];
                #pragma unroll
                for (int f = 0; f < 8; f++)
                    wv4[f] = *(const float4*)&wsk[f * OUT_C + (og << 2)];
                const float* wvf = reinterpret_cast<const float*>(wv4);  // [f*4 + oi]
                const float4 wb4 = *(const float4*)&s_wb[kk * OUT_C + (og << 2)];
                const float* wbf = reinterpret_cast<const float*>(&wb4); // [oi]

                #pragma unroll
                for (int p = 0; p < TILE_H; p++) {
                    const int idx = (p + kh) * PADW + pg + kw;
                    const float xv = s_x[idx];
                    const float4 b0 = *(const float4*)&s_b[idx * BSTRIDE];
                    const float4 b1 = *(const float4*)&s_b[idx * BSTRIDE + 4];
                    const float bf[8] = { b0.x, b0.y, b0.z, b0.w,
                                          b1.x, b1.y, b1.z, b1.w };
                    #pragma unroll
                    for (int oi = 0; oi < 4; oi++) {
                        float t = accS[oi][p];
                        #pragma unroll
                        for (int f = 0; f < 8; f++)
                            t = fmaf(bf[f], wvf[f * 4 + oi], t);
                        accS[oi][p] = t;
                        accB[oi][p] = fmaf(xv, wbf[oi], accB[oi][p]);
                    }
                }
            }
        }
    }

    // ---- write raw partial sums (activation applied in combine) ----
    const int base = split * NOUT + b * (OUT_C * HH * WWID);
    #pragma unroll
    for (int oi = 0; oi < 4; oi++) {
        const int o = (og << 2) + oi;
        #pragma unroll
        for (int p = 0; p < TILE_H; p++) {
            const int idx = base + (o * HH + th0 + p) * WWID + tw0 + pg;
            g_partS[idx] = accS[oi][p];
            g_partB[idx] = accB[oi][p];
        }
    }
}

__global__ __launch_bounds__(256)
void kan_combine_kernel(const float* __restrict__ scaler, float* __restrict__ out)
{
    const int idx = blockIdx.x * blockDim.x + threadIdx.x;
    if (idx >= NOUT) return;
    const int o = (idx / (HH * WWID)) & (OUT_C - 1);
    const float zs = g_partS[idx] + g_partS[idx + NOUT];
    const float zb = g_partB[idx] + g_partB[idx + NOUT];
    const float sil = zb / (1.f + expf(-zb));
    out[idx] = fmaf(scaler[o], zs, sil);
}

extern "C" void kernel_launch(void* const* d_in, const int* in_sizes, int n_in,
                              void* d_out, int out_size)
{
    const float* x      = (const float*)d_in[0];
    const float* wb     = (const float*)d_in[1];
    const float* ws     = (const float*)d_in[2];
    const float* scaler = (const float*)d_in[3];
    float* out = (float*)d_out;

    kan_reorg_kernel<<<(IN_C * 9 * 8 * OUT_C + 255) / 256, 256>>>(ws, wb);

    dim3 grid(WWID / TILE_W, HH / TILE_H, BB * NSPLIT);   // (7, 7, 8) = 392 blocks
    kan_partial_kernel<<<grid, 128>>>(x);

    kan_combine_kernel<<<(NOUT + 255) / 256, 256>>>(scaler, out);
}